// round 11
// baseline (speedup 1.0000x reference)
#include <cuda_runtime.h>
#include <cuda_fp16.h>
#include <math.h>
#include <stdint.h>

#define B_TOK 2048
#define D_DIM 2048
#define N_EXP 16
#define TOPK  2

#define BM 64
#define BN 64
#define BK 32
#define NT (D_DIM / BK)
#define ASTRIDE 20                         // A: [m][kpair], kpair<16
#define BSTRIDE 72                         // B: [kpair][n], n<64
#define A_WORDS (BM * ASTRIDE)             // 1280
#define B_WORDS (16 * BSTRIDE)             // 1152
#define STAGE_WORDS (A_WORDS + B_WORDS)    // 2432
#define SMEM_FORCE 78000                   // forces exactly 2 CTAs/SM (228KB/78KB)

__device__ int    d_count[N_EXP];
__device__ int    d_fill[N_EXP];
__device__ int    d_offset[N_EXP + 1];
__device__ int    d_te[B_TOK * TOPK];
__device__ float  d_tw[B_TOK * TOPK];
__device__ int    d_tok[B_TOK * TOPK];
__device__ int    d_slot[B_TOK * TOPK];
__device__ float  d_imp[N_EXP];
__device__ __half d_H[(size_t)B_TOK * TOPK * D_DIM];   // fp16 hidden (16 MB)
__device__ __half d_Y[(size_t)B_TOK * TOPK * D_DIM];   // fp16 expert out (16 MB)

__device__ __forceinline__ uint32_t pack_h2(float a, float b) {
    __half2 h = __floats2half2_rn(a, b);
    return *(uint32_t*)&h;
}
__device__ __forceinline__ void mma_f16(float& c0, float& c1, float& c2, float& c3,
                                        uint32_t a0, uint32_t a1, uint32_t a2, uint32_t a3,
                                        uint32_t b0, uint32_t b1) {
    asm volatile(
        "mma.sync.aligned.m16n8k16.row.col.f32.f16.f16.f32 "
        "{%0,%1,%2,%3}, {%4,%5,%6,%7}, {%8,%9}, {%0,%1,%2,%3};"
        : "+f"(c0), "+f"(c1), "+f"(c2), "+f"(c3)
        : "r"(a0), "r"(a1), "r"(a2), "r"(a3), "r"(b0), "r"(b1));
}

// ---------------- gating: 512 blocks x 128 thr, 4 tokens/block ----------------
__global__ void __launch_bounds__(128)
k_gate(const float* __restrict__ x, const float* __restrict__ Wg,
       const float* __restrict__ bg) {
    int tid = threadIdx.x;
    int b0 = blockIdx.x * 4;
    const float* xp = x + (size_t)b0 * D_DIM;

    float acc[4][N_EXP];
#pragma unroll
    for (int j = 0; j < 4; j++)
#pragma unroll
        for (int e = 0; e < N_EXP; e++) acc[j][e] = 0.0f;

    for (int d = tid; d < D_DIM; d += 128) {
        const float4* w = (const float4*)(Wg + (size_t)d * N_EXP);
        float4 w0 = w[0], w1 = w[1], w2 = w[2], w3 = w[3];
        float xv[4];
#pragma unroll
        for (int j = 0; j < 4; j++) xv[j] = xp[(size_t)j * D_DIM + d];
#pragma unroll
        for (int j = 0; j < 4; j++) {
            acc[j][0]  += xv[j] * w0.x;  acc[j][1]  += xv[j] * w0.y;
            acc[j][2]  += xv[j] * w0.z;  acc[j][3]  += xv[j] * w0.w;
            acc[j][4]  += xv[j] * w1.x;  acc[j][5]  += xv[j] * w1.y;
            acc[j][6]  += xv[j] * w1.z;  acc[j][7]  += xv[j] * w1.w;
            acc[j][8]  += xv[j] * w2.x;  acc[j][9]  += xv[j] * w2.y;
            acc[j][10] += xv[j] * w2.z;  acc[j][11] += xv[j] * w2.w;
            acc[j][12] += xv[j] * w3.x;  acc[j][13] += xv[j] * w3.y;
            acc[j][14] += xv[j] * w3.z;  acc[j][15] += xv[j] * w3.w;
        }
    }
#pragma unroll
    for (int j = 0; j < 4; j++)
#pragma unroll
        for (int e = 0; e < N_EXP; e++)
#pragma unroll
            for (int o = 16; o > 0; o >>= 1)
                acc[j][e] += __shfl_down_sync(0xffffffffu, acc[j][e], o);

    __shared__ float sw[4][4][N_EXP];
    __shared__ float ssc[4][N_EXP];
    int warp = tid >> 5, lane = tid & 31;
    if (lane == 0)
#pragma unroll
        for (int j = 0; j < 4; j++)
#pragma unroll
            for (int e = 0; e < N_EXP; e++) sw[warp][j][e] = acc[j][e];
    __syncthreads();
    if (tid < 64) {
        int j = tid >> 4, e = tid & 15;
        ssc[j][e] = sw[0][j][e] + sw[1][j][e] + sw[2][j][e] + sw[3][j][e] + bg[e];
    }
    __syncthreads();

    if (tid < 4) {
        int b = b0 + tid;
        const float* sc = ssc[tid];
        float v1 = -1e30f; int i1 = 0;
#pragma unroll
        for (int e = 0; e < N_EXP; e++) if (sc[e] > v1) { v1 = sc[e]; i1 = e; }
        float v2 = -1e30f; int i2 = 0;
#pragma unroll
        for (int e = 0; e < N_EXP; e++) if (e != i1 && sc[e] > v2) { v2 = sc[e]; i2 = e; }
        float p = __expf(v2 - v1);
        float inv2 = 1.0f / (1.0f + p);
        d_te[b*2+0] = i1; d_te[b*2+1] = i2;
        d_tw[b*2+0] = inv2; d_tw[b*2+1] = p * inv2;
        atomicAdd(&d_count[i1], 1);
        atomicAdd(&d_count[i2], 1);
        float ssum = 0.0f, pe[N_EXP];
#pragma unroll
        for (int e = 0; e < N_EXP; e++) { pe[e] = expf(sc[e] - v1); ssum += pe[e]; }
        float invs = 1.0f / ssum;
#pragma unroll
        for (int e = 0; e < N_EXP; e++) atomicAdd(&d_imp[e], pe[e] * invs);
    }
}

// scan + losses; then self-clean counters for the next (graph-replayed) launch
__global__ void k_scan(float* out, int out_size) {
    if (threadIdx.x != 0 || blockIdx.x != 0) return;
    int off = 0; float sum = 0.0f;
    for (int e = 0; e < N_EXP; e++) {
        d_offset[e] = off; off += d_count[e]; sum += (float)d_count[e];
    }
    d_offset[N_EXP] = off;
    float meanl = sum / (float)N_EXP, varl = 0.0f;
    for (int e = 0; e < N_EXP; e++) {
        float dd = (float)d_count[e] - meanl; varl += dd * dd;
    }
    out[out_size - 2] = (varl / (float)(N_EXP - 1)) / (float)B_TOK;
    float mi = 0.0f;
    for (int e = 0; e < N_EXP; e++) mi += d_imp[e];
    mi /= (float)N_EXP;
    float vi = 0.0f;
    for (int e = 0; e < N_EXP; e++) {
        float dd = d_imp[e] - mi; vi += dd * dd;
    }
    out[out_size - 1] = (vi / (float)(N_EXP - 1)) / (mi + 1e-8f);
    // self-clean for next launch (gate/scatter of this launch already consumed)
    for (int e = 0; e < N_EXP; e++) { d_count[e] = 0; d_imp[e] = 0.0f; d_fill[e] = 0; }
}

__global__ void k_scatter() {
    int b = blockIdx.x * blockDim.x + threadIdx.x;
    if (b >= B_TOK) return;
#pragma unroll
    for (int k = 0; k < TOPK; k++) {
        int e = d_te[b*2+k];
        int pos = d_offset[e] + atomicAdd(&d_fill[e], 1);
        d_tok[pos] = b;
        d_slot[b*2+k] = pos;
    }
}

// 64x64x32 tile, 256 thr (8 warps: 2m x 4n, warp tile 32x16)
// MODE 0: d_H = relu(gather(x) @ W1 + b1);  MODE 1: d_Y = H @ W2 + b2
template <int MODE>
__global__ void __launch_bounds__(256, 2)
k_moe_gemm(const float* __restrict__ x, const float* __restrict__ W,
           const float* __restrict__ bias) {
    int e = blockIdx.z;
    int off = d_offset[e];
    int ne = d_offset[e+1] - off;
    int row0 = blockIdx.y * BM;
    if (row0 >= ne) return;
    int col0 = blockIdx.x * BN;
    const float* Bm = W + (size_t)e * D_DIM * D_DIM;

    extern __shared__ uint32_t smdyn[];

    int tid = threadIdx.x;
    int lane = tid & 31, wid = tid >> 5;
    int warpM = (wid & 1) * 32;
    int warpN = (wid >> 1) * 16;

    // A: row m = tid>>2 (0..63), k-chunk (tid&3)*8
    int am = tid >> 2;
    int agr = row0 + am; if (agr >= ne) agr = ne - 1;
    const float*  pAf = 0;
    const __half* pAh = 0;
    if (MODE == 0) pAf = x + (size_t)d_tok[off + agr] * D_DIM + (tid & 3) * 8;
    else           pAh = d_H + (size_t)(off + agr) * D_DIM + (tid & 3) * 8;
    int akp0 = (tid & 3) * 4;              // 4 u32 (8 halves)

    // B: kpair kp = tid>>4 (0..15), n chunk (tid&15)*4
    int bkp = tid >> 4;
    int bn0 = (tid & 15) * 4;
    const float* pB0 = Bm + (size_t)(2 * bkp) * D_DIM + col0 + bn0;

    float acc[2][2][4];
#pragma unroll
    for (int i = 0; i < 2; i++)
#pragma unroll
        for (int j = 0; j < 2; j++)
#pragma unroll
            for (int c = 0; c < 4; c++) acc[i][j][c] = 0.0f;

    float4 rA0, rA1;       // MODE 0: 8 floats
    uint4  rAh;            // MODE 1: 8 halves
    float4 rB0, rB1;       // B rows 2kp, 2kp+1 (4 floats each)
    if (MODE == 0) { rA0 = *((const float4*)pAf); rA1 = *((const float4*)pAf + 1); }
    else           { rAh = *((const uint4*)pAh); }
    rB0 = *((const float4*)pB0);
    rB1 = *((const float4*)(pB0 + D_DIM));

    // prologue store -> stage 0
    {
        uint32_t* sA = smdyn;
        uint32_t* sB = smdyn + A_WORDS;
        if (MODE == 0) {
            uint4 u;
            u.x = pack_h2(rA0.x, rA0.y); u.y = pack_h2(rA0.z, rA0.w);
            u.z = pack_h2(rA1.x, rA1.y); u.w = pack_h2(rA1.z, rA1.w);
            *(uint4*)&sA[am * ASTRIDE + akp0] = u;
        } else {
            *(uint4*)&sA[am * ASTRIDE + akp0] = rAh;
        }
        uint4 ub;
        ub.x = pack_h2(rB0.x, rB1.x); ub.y = pack_h2(rB0.y, rB1.y);
        ub.z = pack_h2(rB0.z, rB1.z); ub.w = pack_h2(rB0.w, rB1.w);
        *(uint4*)&sB[bkp * BSTRIDE + bn0] = ub;
    }
    __syncthreads();

    for (int t = 0; t < NT; t++) {
        uint32_t* sA = smdyn + (t & 1) * STAGE_WORDS;
        uint32_t* sB = sA + A_WORDS;

        if (t + 1 < NT) {
            int k0 = (t + 1) * BK;
            if (MODE == 0) { rA0 = *((const float4*)(pAf + k0));
                             rA1 = *((const float4*)(pAf + k0) + 1); }
            else           { rAh = *((const uint4*)(pAh + k0)); }
            const float* pBk = pB0 + (size_t)k0 * D_DIM;
            rB0 = *((const float4*)pBk);
            rB1 = *((const float4*)(pBk + D_DIM));
        }

#pragma unroll
        for (int ks = 0; ks < 2; ks++) {
            int kp8 = ks * 8;
            int c = kp8 + (lane & 3);
            uint32_t a[2][4];
#pragma unroll
            for (int mt = 0; mt < 2; mt++) {
                int r = warpM + mt * 16 + (lane >> 2);
                a[mt][0] = sA[r * ASTRIDE + c];
                a[mt][1] = sA[(r + 8) * ASTRIDE + c];
                a[mt][2] = sA[r * ASTRIDE + c + 4];
                a[mt][3] = sA[(r + 8) * ASTRIDE + c + 4];
            }
#pragma unroll
            for (int nt = 0; nt < 2; nt++) {
                int n = warpN + nt * 8 + (lane >> 2);
                uint32_t b0 = sB[c * BSTRIDE + n];
                uint32_t b1v = sB[(c + 4) * BSTRIDE + n];
#pragma unroll
                for (int mt = 0; mt < 2; mt++)
                    mma_f16(acc[mt][nt][0], acc[mt][nt][1], acc[mt][nt][2], acc[mt][nt][3],
                            a[mt][0], a[mt][1], a[mt][2], a[mt][3], b0, b1v);
            }
        }

        if (t + 1 < NT) {
            uint32_t* nA = smdyn + ((t + 1) & 1) * STAGE_WORDS;
            uint32_t* nB = nA + A_WORDS;
            if (MODE == 0) {
                uint4 u;
                u.x = pack_h2(rA0.x, rA0.y); u.y = pack_h2(rA0.z, rA0.w);
                u.z = pack_h2(rA1.x, rA1.y); u.w = pack_h2(rA1.z, rA1.w);
                *(uint4*)&nA[am * ASTRIDE + akp0] = u;
            } else {
                *(uint4*)&nA[am * ASTRIDE + akp0] = rAh;
            }
            uint4 ub;
            ub.x = pack_h2(rB0.x, rB1.x); ub.y = pack_h2(rB0.y, rB1.y);
            ub.z = pack_h2(rB0.z, rB1.z); ub.w = pack_h2(rB0.w, rB1.w);
            *(uint4*)&nB[bkp * BSTRIDE + bn0] = ub;
        }
        __syncthreads();
    }

    // epilogue: bias (+relu), fp16 stores, no atomics
#pragma unroll
    for (int nt = 0; nt < 2; nt++) {
        int c = col0 + warpN + nt * 8 + (lane & 3) * 2;
        float2 bb = *(const float2*)(bias + e * D_DIM + c);
#pragma unroll
        for (int mt = 0; mt < 2; mt++) {
            int r0 = row0 + warpM + mt * 16 + (lane >> 2);
            int r1 = r0 + 8;
            if (r0 < ne) {
                float v0 = acc[mt][nt][0] + bb.x;
                float v1 = acc[mt][nt][1] + bb.y;
                if (MODE == 0) { v0 = fmaxf(v0, 0.f); v1 = fmaxf(v1, 0.f); }
                __half* dst = (MODE == 0 ? d_H : d_Y) + (size_t)(off + r0) * D_DIM + c;
                *(__half2*)dst = __floats2half2_rn(v0, v1);
            }
            if (r1 < ne) {
                float v2 = acc[mt][nt][2] + bb.x;
                float v3 = acc[mt][nt][3] + bb.y;
                if (MODE == 0) { v2 = fmaxf(v2, 0.f); v3 = fmaxf(v3, 0.f); }
                __half* dst = (MODE == 0 ? d_H : d_Y) + (size_t)(off + r1) * D_DIM + c;
                *(__half2*)dst = __floats2half2_rn(v2, v3);
            }
        }
    }
}

// combine: out[b] = w0*Y[s0] + w1*Y[s1]  (Y fp16 -> fp32 math)
__global__ void k_combine(float* __restrict__ out) {
    int b = blockIdx.x;
    int s0 = d_slot[b*2+0], s1 = d_slot[b*2+1];
    float w0 = d_tw[b*2+0], w1 = d_tw[b*2+1];
    const __half2* y0 = (const __half2*)(d_Y + (size_t)s0 * D_DIM);
    const __half2* y1 = (const __half2*)(d_Y + (size_t)s1 * D_DIM);
    float2* o = (float2*)(out + (size_t)b * D_DIM);
    for (int i = threadIdx.x; i < D_DIM / 2; i += blockDim.x) {
        float2 a = __half22float2(y0[i]);
        float2 c = __half22float2(y1[i]);
        float2 r;
        r.x = w0 * a.x + w1 * c.x;
        r.y = w0 * a.y + w1 * c.y;
        o[i] = r;
    }
}

extern "C" void kernel_launch(void* const* d_in, const int* in_sizes, int n_in,
                              void* d_out, int out_size) {
    const float* x  = (const float*)d_in[0];
    const float* W1 = (const float*)d_in[1];
    const float* b1 = (const float*)d_in[2];
    const float* W2 = (const float*)d_in[3];
    const float* b2 = (const float*)d_in[4];
    const float* Wg = (const float*)d_in[5];
    const float* bg = (const float*)d_in[6];
    float* out = (float*)d_out;

    cudaFuncSetAttribute(k_moe_gemm<0>, cudaFuncAttributeMaxDynamicSharedMemorySize, SMEM_FORCE);
    cudaFuncSetAttribute(k_moe_gemm<1>, cudaFuncAttributeMaxDynamicSharedMemorySize, SMEM_FORCE);

    k_gate<<<B_TOK / 4, 128>>>(x, Wg, bg);
    k_scan<<<1, 32>>>(out, out_size);
    k_scatter<<<(B_TOK + 255) / 256, 256>>>();

    dim3 grid(D_DIM / BN, (B_TOK + BM - 1) / BM, N_EXP);   // (32, 32, 16)
    k_moe_gemm<0><<<grid, 256, SMEM_FORCE>>>(x, W1, b1);
    k_moe_gemm<1><<<grid, 256, SMEM_FORCE>>>(x, W2, b2);
    k_combine<<<B_TOK, 128>>>(out);
}

// round 12
// speedup vs baseline: 1.3413x; 1.3413x over previous
#include <cuda_runtime.h>
#include <cuda_fp16.h>
#include <math.h>
#include <stdint.h>

#define B_TOK 2048
#define D_DIM 2048
#define N_EXP 16
#define TOPK  2

#define BM 128
#define BN 128
#define BK 32
#define NT (D_DIM / BK)
#define ASTRIDE 20                        // A: [m][kpair], kpair<16, stride 20 u32
#define BSTRIDE 136                       // B: [kpair][n], n<128, stride 136 u32
#define A_WORDS (BM * ASTRIDE)            // 2560
#define B_WORDS (16 * BSTRIDE)            // 2176
#define STAGE_WORDS (A_WORDS + B_WORDS)   // 4736
#define SMEM_BYTES (2 * STAGE_WORDS * 4)  // 37888

__device__ int    d_count[N_EXP];
__device__ int    d_fill[N_EXP];
__device__ int    d_offset[N_EXP + 1];
__device__ int    d_te[B_TOK * TOPK];
__device__ float  d_tw[B_TOK * TOPK];
__device__ int    d_tok[B_TOK * TOPK];
__device__ int    d_slot[B_TOK * TOPK];
__device__ float  d_imp[N_EXP];
__device__ __half d_H[(size_t)B_TOK * TOPK * D_DIM];   // fp16 hidden (16 MB)
__device__ __half d_Y[(size_t)B_TOK * TOPK * D_DIM];   // fp16 expert out (16 MB)

__device__ __forceinline__ uint32_t pack_h2(float a, float b) {
    __half2 h = __floats2half2_rn(a, b);
    return *(uint32_t*)&h;
}
__device__ __forceinline__ void mma_f16(float& c0, float& c1, float& c2, float& c3,
                                        uint32_t a0, uint32_t a1, uint32_t a2, uint32_t a3,
                                        uint32_t b0, uint32_t b1) {
    asm volatile(
        "mma.sync.aligned.m16n8k16.row.col.f32.f16.f16.f32 "
        "{%0,%1,%2,%3}, {%4,%5,%6,%7}, {%8,%9}, {%0,%1,%2,%3};"
        : "+f"(c0), "+f"(c1), "+f"(c2), "+f"(c3)
        : "r"(a0), "r"(a1), "r"(a2), "r"(a3), "r"(b0), "r"(b1));
}

// ---------------- gating: 512 blocks x 128 thr, 4 tokens/block ----------------
__global__ void __launch_bounds__(128)
k_gate(const float* __restrict__ x, const float* __restrict__ Wg,
       const float* __restrict__ bg) {
    int tid = threadIdx.x;
    int b0 = blockIdx.x * 4;
    const float* xp = x + (size_t)b0 * D_DIM;

    float acc[4][N_EXP];
#pragma unroll
    for (int j = 0; j < 4; j++)
#pragma unroll
        for (int e = 0; e < N_EXP; e++) acc[j][e] = 0.0f;

    for (int d = tid; d < D_DIM; d += 128) {
        const float4* w = (const float4*)(Wg + (size_t)d * N_EXP);
        float4 w0 = w[0], w1 = w[1], w2 = w[2], w3 = w[3];
        float xv[4];
#pragma unroll
        for (int j = 0; j < 4; j++) xv[j] = xp[(size_t)j * D_DIM + d];
#pragma unroll
        for (int j = 0; j < 4; j++) {
            acc[j][0]  += xv[j] * w0.x;  acc[j][1]  += xv[j] * w0.y;
            acc[j][2]  += xv[j] * w0.z;  acc[j][3]  += xv[j] * w0.w;
            acc[j][4]  += xv[j] * w1.x;  acc[j][5]  += xv[j] * w1.y;
            acc[j][6]  += xv[j] * w1.z;  acc[j][7]  += xv[j] * w1.w;
            acc[j][8]  += xv[j] * w2.x;  acc[j][9]  += xv[j] * w2.y;
            acc[j][10] += xv[j] * w2.z;  acc[j][11] += xv[j] * w2.w;
            acc[j][12] += xv[j] * w3.x;  acc[j][13] += xv[j] * w3.y;
            acc[j][14] += xv[j] * w3.z;  acc[j][15] += xv[j] * w3.w;
        }
    }
#pragma unroll
    for (int j = 0; j < 4; j++)
#pragma unroll
        for (int e = 0; e < N_EXP; e++)
#pragma unroll
            for (int o = 16; o > 0; o >>= 1)
                acc[j][e] += __shfl_down_sync(0xffffffffu, acc[j][e], o);

    __shared__ float sw[4][4][N_EXP];
    __shared__ float ssc[4][N_EXP];
    int warp = tid >> 5, lane = tid & 31;
    if (lane == 0)
#pragma unroll
        for (int j = 0; j < 4; j++)
#pragma unroll
            for (int e = 0; e < N_EXP; e++) sw[warp][j][e] = acc[j][e];
    __syncthreads();
    if (tid < 64) {
        int j = tid >> 4, e = tid & 15;
        ssc[j][e] = sw[0][j][e] + sw[1][j][e] + sw[2][j][e] + sw[3][j][e] + bg[e];
    }
    __syncthreads();

    if (tid < 4) {
        int b = b0 + tid;
        const float* sc = ssc[tid];
        float v1 = -1e30f; int i1 = 0;
#pragma unroll
        for (int e = 0; e < N_EXP; e++) if (sc[e] > v1) { v1 = sc[e]; i1 = e; }
        float v2 = -1e30f; int i2 = 0;
#pragma unroll
        for (int e = 0; e < N_EXP; e++) if (e != i1 && sc[e] > v2) { v2 = sc[e]; i2 = e; }
        float p = __expf(v2 - v1);
        float inv2 = 1.0f / (1.0f + p);
        d_te[b*2+0] = i1; d_te[b*2+1] = i2;
        d_tw[b*2+0] = inv2; d_tw[b*2+1] = p * inv2;
        atomicAdd(&d_count[i1], 1);
        atomicAdd(&d_count[i2], 1);
        float ssum = 0.0f, pe[N_EXP];
#pragma unroll
        for (int e = 0; e < N_EXP; e++) { pe[e] = expf(sc[e] - v1); ssum += pe[e]; }
        float invs = 1.0f / ssum;
#pragma unroll
        for (int e = 0; e < N_EXP; e++) atomicAdd(&d_imp[e], pe[e] * invs);
    }
}

// scan + losses; self-cleans counters for the next graph replay
__global__ void k_scan(float* out, int out_size) {
    if (threadIdx.x != 0 || blockIdx.x != 0) return;
    int off = 0; float sum = 0.0f;
    for (int e = 0; e < N_EXP; e++) {
        d_offset[e] = off; off += d_count[e]; sum += (float)d_count[e];
    }
    d_offset[N_EXP] = off;
    float meanl = sum / (float)N_EXP, varl = 0.0f;
    for (int e = 0; e < N_EXP; e++) {
        float dd = (float)d_count[e] - meanl; varl += dd * dd;
    }
    out[out_size - 2] = (varl / (float)(N_EXP - 1)) / (float)B_TOK;
    float mi = 0.0f;
    for (int e = 0; e < N_EXP; e++) mi += d_imp[e];
    mi /= (float)N_EXP;
    float vi = 0.0f;
    for (int e = 0; e < N_EXP; e++) {
        float dd = d_imp[e] - mi; vi += dd * dd;
    }
    out[out_size - 1] = (vi / (float)(N_EXP - 1)) / (mi + 1e-8f);
    for (int e = 0; e < N_EXP; e++) { d_count[e] = 0; d_imp[e] = 0.0f; d_fill[e] = 0; }
}

__global__ void k_scatter() {
    int b = blockIdx.x * blockDim.x + threadIdx.x;
    if (b >= B_TOK) return;
#pragma unroll
    for (int k = 0; k < TOPK; k++) {
        int e = d_te[b*2+k];
        int pos = d_offset[e] + atomicAdd(&d_fill[e], 1);
        d_tok[pos] = b;
        d_slot[b*2+k] = pos;
    }
}

// 128x128x32, 8 warps (4m x 2n), warp 32x64; fp16 m16n8k16
// MODE 0: d_H = relu(gather(x) @ W1 + b1);  MODE 1: d_Y = H @ W2 + b2
template <int MODE>
__global__ void __launch_bounds__(256, 2)
k_moe_gemm(const float* __restrict__ x, const float* __restrict__ W,
           const float* __restrict__ bias) {
    int e = blockIdx.z;
    int off = d_offset[e];
    int ne = d_offset[e+1] - off;
    int row0 = blockIdx.y * BM;
    if (row0 >= ne) return;
    int col0 = blockIdx.x * BN;
    const float* Bm = W + (size_t)e * D_DIM * D_DIM;

    extern __shared__ uint32_t smdyn[];

    int tid = threadIdx.x;
    int lane = tid & 31, wid = tid >> 5;
    int wm = (wid & 3) * 32;
    int wn = (wid >> 2) * 64;

    int am = tid >> 1;
    int agr = row0 + am; if (agr >= ne) agr = ne - 1;
    const float*  pAf = 0;
    const __half* pAh = 0;
    if (MODE == 0) pAf = x + (size_t)d_tok[off + agr] * D_DIM + (tid & 1) * 16;
    else           pAh = d_H + (size_t)(off + agr) * D_DIM + (tid & 1) * 16;
    int akp0 = (tid & 1) * 8;

    int bkp = tid >> 4;
    int bn0 = (tid & 15) * 8;
    const float* pB0 = Bm + (size_t)(2 * bkp) * D_DIM + col0 + bn0;

    float acc[2][8][4];
#pragma unroll
    for (int i = 0; i < 2; i++)
#pragma unroll
        for (int j = 0; j < 8; j++)
#pragma unroll
            for (int c = 0; c < 4; c++) acc[i][j][c] = 0.0f;

    float4 rA[4];
    uint4  rAh[2];
    float4 rB0[2], rB1[2];
    if (MODE == 0) {
#pragma unroll
        for (int q = 0; q < 4; q++) rA[q] = *((const float4*)pAf + q);
    } else {
        rAh[0] = *((const uint4*)pAh); rAh[1] = *((const uint4*)pAh + 1);
    }
#pragma unroll
    for (int q = 0; q < 2; q++) { rB0[q] = *((const float4*)pB0 + q);
                                  rB1[q] = *((const float4*)(pB0 + D_DIM) + q); }

    // prologue store -> stage 0
    {
        uint32_t* sA = smdyn;
        uint32_t* sB = smdyn + A_WORDS;
        if (MODE == 0) {
            uint4 ua0, ua1;
            ua0.x = pack_h2(rA[0].x, rA[0].y); ua0.y = pack_h2(rA[0].z, rA[0].w);
            ua0.z = pack_h2(rA[1].x, rA[1].y); ua0.w = pack_h2(rA[1].z, rA[1].w);
            ua1.x = pack_h2(rA[2].x, rA[2].y); ua1.y = pack_h2(rA[2].z, rA[2].w);
            ua1.z = pack_h2(rA[3].x, rA[3].y); ua1.w = pack_h2(rA[3].z, rA[3].w);
            *(uint4*)&sA[am * ASTRIDE + akp0]     = ua0;
            *(uint4*)&sA[am * ASTRIDE + akp0 + 4] = ua1;
        } else {
            *(uint4*)&sA[am * ASTRIDE + akp0]     = rAh[0];
            *(uint4*)&sA[am * ASTRIDE + akp0 + 4] = rAh[1];
        }
        uint4 ub0, ub1;
        ub0.x = pack_h2(rB0[0].x, rB1[0].x); ub0.y = pack_h2(rB0[0].y, rB1[0].y);
        ub0.z = pack_h2(rB0[0].z, rB1[0].z); ub0.w = pack_h2(rB0[0].w, rB1[0].w);
        ub1.x = pack_h2(rB0[1].x, rB1[1].x); ub1.y = pack_h2(rB0[1].y, rB1[1].y);
        ub1.z = pack_h2(rB0[1].z, rB1[1].z); ub1.w = pack_h2(rB0[1].w, rB1[1].w);
        *(uint4*)&sB[bkp * BSTRIDE + bn0]     = ub0;
        *(uint4*)&sB[bkp * BSTRIDE + bn0 + 4] = ub1;
    }
    __syncthreads();

    for (int t = 0; t < NT; t++) {
        uint32_t* sA = smdyn + (t & 1) * STAGE_WORDS;
        uint32_t* sB = sA + A_WORDS;

        if (t + 1 < NT) {
            int k0 = (t + 1) * BK;
            if (MODE == 0) {
#pragma unroll
                for (int q = 0; q < 4; q++) rA[q] = *((const float4*)(pAf + k0) + q);
            } else {
                rAh[0] = *((const uint4*)(pAh + k0));
                rAh[1] = *((const uint4*)(pAh + k0) + 1);
            }
            const float* pBk = pB0 + (size_t)k0 * D_DIM;
#pragma unroll
            for (int q = 0; q < 2; q++) { rB0[q] = *((const float4*)pBk + q);
                                          rB1[q] = *((const float4*)(pBk + D_DIM) + q); }
        }

#pragma unroll
        for (int ks = 0; ks < 2; ks++) {
            int kp8 = ks * 8;
            uint32_t a[2][4];
#pragma unroll
            for (int mt = 0; mt < 2; mt++) {
                int r = wm + mt * 16 + (lane >> 2);
                int c = kp8 + (lane & 3);
                a[mt][0] = sA[r * ASTRIDE + c];
                a[mt][1] = sA[(r + 8) * ASTRIDE + c];
                a[mt][2] = sA[r * ASTRIDE + c + 4];
                a[mt][3] = sA[(r + 8) * ASTRIDE + c + 4];
            }
#pragma unroll
            for (int nt = 0; nt < 8; nt++) {
                int n = wn + nt * 8 + (lane >> 2);
                uint32_t b0 = sB[(kp8 + (lane & 3)) * BSTRIDE + n];
                uint32_t b1v = sB[(kp8 + (lane & 3) + 4) * BSTRIDE + n];
#pragma unroll
                for (int mt = 0; mt < 2; mt++)
                    mma_f16(acc[mt][nt][0], acc[mt][nt][1], acc[mt][nt][2], acc[mt][nt][3],
                            a[mt][0], a[mt][1], a[mt][2], a[mt][3], b0, b1v);
            }
        }

        if (t + 1 < NT) {
            uint32_t* nA = smdyn + ((t + 1) & 1) * STAGE_WORDS;
            uint32_t* nB = nA + A_WORDS;
            if (MODE == 0) {
                uint4 ua0, ua1;
                ua0.x = pack_h2(rA[0].x, rA[0].y); ua0.y = pack_h2(rA[0].z, rA[0].w);
                ua0.z = pack_h2(rA[1].x, rA[1].y); ua0.w = pack_h2(rA[1].z, rA[1].w);
                ua1.x = pack_h2(rA[2].x, rA[2].y); ua1.y = pack_h2(rA[2].z, rA[2].w);
                ua1.z = pack_h2(rA[3].x, rA[3].y); ua1.w = pack_h2(rA[3].z, rA[3].w);
                *(uint4*)&nA[am * ASTRIDE + akp0]     = ua0;
                *(uint4*)&nA[am * ASTRIDE + akp0 + 4] = ua1;
            } else {
                *(uint4*)&nA[am * ASTRIDE + akp0]     = rAh[0];
                *(uint4*)&nA[am * ASTRIDE + akp0 + 4] = rAh[1];
            }
            uint4 ub0, ub1;
            ub0.x = pack_h2(rB0[0].x, rB1[0].x); ub0.y = pack_h2(rB0[0].y, rB1[0].y);
            ub0.z = pack_h2(rB0[0].z, rB1[0].z); ub0.w = pack_h2(rB0[0].w, rB1[0].w);
            ub1.x = pack_h2(rB0[1].x, rB1[1].x); ub1.y = pack_h2(rB0[1].y, rB1[1].y);
            ub1.z = pack_h2(rB0[1].z, rB1[1].z); ub1.w = pack_h2(rB0[1].w, rB1[1].w);
            *(uint4*)&nB[bkp * BSTRIDE + bn0]     = ub0;
            *(uint4*)&nB[bkp * BSTRIDE + bn0 + 4] = ub1;
        }
        __syncthreads();
    }

    // epilogue: bias (+relu), fp16 stores, no atomics
#pragma unroll
    for (int nt = 0; nt < 8; nt++) {
        int c = col0 + wn + nt * 8 + (lane & 3) * 2;
        float2 bb = *(const float2*)(bias + e * D_DIM + c);
#pragma unroll
        for (int mt = 0; mt < 2; mt++) {
            int r0 = row0 + wm + mt * 16 + (lane >> 2);
            int r1 = r0 + 8;
            if (r0 < ne) {
                float v0 = acc[mt][nt][0] + bb.x;
                float v1 = acc[mt][nt][1] + bb.y;
                if (MODE == 0) { v0 = fmaxf(v0, 0.f); v1 = fmaxf(v1, 0.f); }
                __half* dst = (MODE == 0 ? d_H : d_Y) + (size_t)(off + r0) * D_DIM + c;
                *(__half2*)dst = __floats2half2_rn(v0, v1);
            }
            if (r1 < ne) {
                float v2 = acc[mt][nt][2] + bb.x;
                float v3 = acc[mt][nt][3] + bb.y;
                if (MODE == 0) { v2 = fmaxf(v2, 0.f); v3 = fmaxf(v3, 0.f); }
                __half* dst = (MODE == 0 ? d_H : d_Y) + (size_t)(off + r1) * D_DIM + c;
                *(__half2*)dst = __floats2half2_rn(v2, v3);
            }
        }
    }
}

// combine: out[b] = w0*Y[s0] + w1*Y[s1]  (Y fp16 -> fp32 math)
__global__ void k_combine(float* __restrict__ out) {
    int b = blockIdx.x;
    int s0 = d_slot[b*2+0], s1 = d_slot[b*2+1];
    float w0 = d_tw[b*2+0], w1 = d_tw[b*2+1];
    const __half2* y0 = (const __half2*)(d_Y + (size_t)s0 * D_DIM);
    const __half2* y1 = (const __half2*)(d_Y + (size_t)s1 * D_DIM);
    float2* o = (float2*)(out + (size_t)b * D_DIM);
    for (int i = threadIdx.x; i < D_DIM / 2; i += blockDim.x) {
        float2 a = __half22float2(y0[i]);
        float2 c = __half22float2(y1[i]);
        float2 r;
        r.x = w0 * a.x + w1 * c.x;
        r.y = w0 * a.y + w1 * c.y;
        o[i] = r;
    }
}

extern "C" void kernel_launch(void* const* d_in, const int* in_sizes, int n_in,
                              void* d_out, int out_size) {
    const float* x  = (const float*)d_in[0];
    const float* W1 = (const float*)d_in[1];
    const float* b1 = (const float*)d_in[2];
    const float* W2 = (const float*)d_in[3];
    const float* b2 = (const float*)d_in[4];
    const float* Wg = (const float*)d_in[5];
    const float* bg = (const float*)d_in[6];
    float* out = (float*)d_out;

    k_gate<<<B_TOK / 4, 128>>>(x, Wg, bg);
    k_scan<<<1, 32>>>(out, out_size);
    k_scatter<<<(B_TOK + 255) / 256, 256>>>();

    dim3 grid(D_DIM / BN, (B_TOK + BM - 1) / BM, N_EXP);   // (16, 16, 16)
    k_moe_gemm<0><<<grid, 256, SMEM_BYTES>>>(x, W1, b1);
    k_moe_gemm<1><<<grid, 256, SMEM_BYTES>>>(x, W2, b2);
    k_combine<<<B_TOK, 128>>>(out);
}